// round 1
// baseline (speedup 1.0000x reference)
#include <cuda_runtime.h>

#define S_LEN   8192
#define BATCH   8
#define DIM     128
#define NB      32            // blocks per batch (S/BS)
#define BS      256           // block size
#define HALO    255
#define WIN     766           // BS + 2*HALO
#define NROWS   (BATCH * S_LEN)   // 65536

// Scratch for projected q,k,v (static device arrays; allocation-free rule)
__device__ float g_q[NROWS * DIM];
__device__ float g_k[NROWS * DIM];
__device__ float g_v[NROWS * DIM];

__device__ __forceinline__ float f4get(const float4& v, int i) {
    return (i == 0) ? v.x : (i == 1) ? v.y : (i == 2) ? v.z : v.w;
}

// ---------------------------------------------------------------------------
// Phase 1: q/k/v = x @ W^T + b.   One matrix per blockIdx.y.
// CTA: 256 threads, tile 128 rows x 128 cols, 8x8 micro per thread.
// smem: w_s [128][132] (full W, padded), x_s [128][36] (32-d chunk, padded)
// ---------------------------------------------------------------------------
#define P1_SMEM ((128 * 132 + 128 * 36) * 4)   // 86016 bytes

__global__ __launch_bounds__(256, 2)
void qkv_proj_kernel(const float* __restrict__ x,
                     const float* __restrict__ Wq, const float* __restrict__ bq,
                     const float* __restrict__ Wk, const float* __restrict__ bk,
                     const float* __restrict__ Wv, const float* __restrict__ bv)
{
    extern __shared__ float sm[];
    float* w_s = sm;                  // [128][132]
    float* x_s = sm + 128 * 132;      // [128][36]

    const int m = blockIdx.y;
    const float* W    = (m == 0) ? Wq : (m == 1) ? Wk : Wv;
    const float* bias = (m == 0) ? bq : (m == 1) ? bk : bv;
    float* outp       = (m == 0) ? g_q : (m == 1) ? g_k : g_v;

    const int tid = threadIdx.x;
    const int tx = tid & 15;
    const int ty = tid >> 4;
    const int r0 = blockIdx.x * 128;

    // Load full W (128x128) into smem, padded rows of 33 float4
    const float4* W4 = (const float4*)W;
    float4* w_s4 = (float4*)w_s;
#pragma unroll
    for (int i = 0; i < 16; i++) {
        int f4 = tid + 256 * i;
        int h = f4 >> 5, d4 = f4 & 31;
        w_s4[h * 33 + d4] = W4[f4];
    }

    float acc[8][8];
#pragma unroll
    for (int r = 0; r < 8; r++)
#pragma unroll
        for (int c = 0; c < 8; c++) acc[r][c] = 0.0f;

    const float4* x4g = (const float4*)x;
    float4* x_s4 = (float4*)x_s;

    for (int kk = 0; kk < 4; kk++) {
        __syncthreads();   // covers w_s on first iter, x_s reuse after
#pragma unroll
        for (int i = 0; i < 4; i++) {
            int f4 = tid + 256 * i;
            int r = f4 >> 3, d4 = f4 & 7;
            x_s4[r * 9 + d4] = x4g[(r0 + r) * 32 + kk * 8 + d4];
        }
        __syncthreads();

#pragma unroll
        for (int d4 = 0; d4 < 8; d4++) {
            float4 xv[8];
#pragma unroll
            for (int r = 0; r < 8; r++) xv[r] = x_s4[(ty * 8 + r) * 9 + d4];
#pragma unroll
            for (int c = 0; c < 8; c++) {
                float4 wv = w_s4[(c * 16 + tx) * 33 + kk * 8 + d4];
#pragma unroll
                for (int r = 0; r < 8; r++) {
                    acc[r][c] += xv[r].x * wv.x;
                    acc[r][c] += xv[r].y * wv.y;
                    acc[r][c] += xv[r].z * wv.z;
                    acc[r][c] += xv[r].w * wv.w;
                }
            }
        }
    }

    // Epilogue: add bias, store
    float bvals[8];
#pragma unroll
    for (int c = 0; c < 8; c++) bvals[c] = bias[c * 16 + tx];
#pragma unroll
    for (int r = 0; r < 8; r++) {
        int row = r0 + ty * 8 + r;
#pragma unroll
        for (int c = 0; c < 8; c++) {
            outp[row * DIM + c * 16 + tx] = acc[r][c] + bvals[c];
        }
    }
}

// ---------------------------------------------------------------------------
// Phase 2: per (batch, block):  M = K_win^T @ V_win;  out = scale * q_blk @ M
// CTA: 256 threads (16x16), one CTA per (b, n).
// smem: M_s [128][132], k_s [32][132], v_s [32][132] (q_s reuses k_s/v_s)
// ---------------------------------------------------------------------------
#define P2_SMEM ((128 * 132 + 2 * 32 * 132) * 4)   // 101376 bytes

__global__ __launch_bounds__(256, 2)
void block_attn_kernel(float* __restrict__ out)
{
    extern __shared__ float sm[];
    float* M_s = sm;                      // [128][132]
    float* k_s = sm + 128 * 132;          // [32][132]
    float* v_s = k_s + 32 * 132;          // [32][132]
    float* q_s = k_s;                     // part B reuse: [128][36] = 4608 floats <= 8448

    const int tid = threadIdx.x;
    const int tx = tid & 15;
    const int ty = tid >> 4;
    const int bn = blockIdx.x;            // b*NB + n
    const int b = bn >> 5;
    const int n = bn & 31;
    const int base = b * S_LEN;           // row base in g_k/g_v/g_q
    const int g0 = n * BS - HALO;         // first window position (may be <0)

    float acc[8][8];
#pragma unroll
    for (int r = 0; r < 8; r++)
#pragma unroll
        for (int c = 0; c < 8; c++) acc[r][c] = 0.0f;

    float4* k_s4 = (float4*)k_s;
    float4* v_s4 = (float4*)v_s;
    const float4* kg4 = (const float4*)g_k;
    const float4* vg4 = (const float4*)g_v;

    // ---- Part A: M = sum over window of k ⊗ v, streamed in chunks of 32 ----
    for (int ci = 0; ci < 24; ci++) {
        __syncthreads();
#pragma unroll
        for (int i = 0; i < 4; i++) {
            int f4 = tid + 256 * i;
            int j = f4 >> 5, d4 = f4 & 31;
            int t = ci * 32 + j;
            int g = g0 + t;
            bool ok = (t < WIN) && (g >= 0) && (g < S_LEN);
            float4 kv = make_float4(0.f, 0.f, 0.f, 0.f);
            float4 vv = make_float4(0.f, 0.f, 0.f, 0.f);
            if (ok) {
                kv = kg4[(base + g) * 32 + d4];
                vv = vg4[(base + g) * 32 + d4];
            }
            k_s4[j * 33 + d4] = kv;
            v_s4[j * 33 + d4] = vv;
        }
        __syncthreads();

#pragma unroll 4
        for (int j = 0; j < 32; j++) {
            float4 ka = k_s4[j * 33 + ty * 2];
            float4 kb = k_s4[j * 33 + ty * 2 + 1];
            float kr[8] = {ka.x, ka.y, ka.z, ka.w, kb.x, kb.y, kb.z, kb.w};
            float vc[8];
#pragma unroll
            for (int c = 0; c < 8; c++) vc[c] = v_s[j * 132 + c * 16 + tx];
#pragma unroll
            for (int r = 0; r < 8; r++)
#pragma unroll
                for (int c = 0; c < 8; c++) acc[r][c] += kr[r] * vc[c];
        }
    }

    // Store M tile to smem (rows ty*8+r, cols c*16+tx)
#pragma unroll
    for (int r = 0; r < 8; r++)
#pragma unroll
        for (int c = 0; c < 8; c++)
            M_s[(ty * 8 + r) * 132 + c * 16 + tx] = acc[r][c];

    // ---- Part B: out = scale * q_blk @ M ----
    const float scale = 0.088388347648318447f;  // 1/sqrt(128)
    const float4* qg4 = (const float4*)g_q;
    float4* q_s4 = (float4*)q_s;
    const int qrow0 = base + n * BS;

    for (int it = 0; it < 2; it++) {
        float oacc[8][8];
#pragma unroll
        for (int r = 0; r < 8; r++)
#pragma unroll
            for (int c = 0; c < 8; c++) oacc[r][c] = 0.0f;

        for (int kk = 0; kk < 4; kk++) {
            __syncthreads();   // protects k_s/v_s (part A) and prior-iter q_s reads; M_s stores precede
#pragma unroll
            for (int i = 0; i < 4; i++) {
                int f4 = tid + 256 * i;
                int r = f4 >> 3, d4 = f4 & 7;
                q_s4[r * 9 + d4] = qg4[(qrow0 + it * 128 + r) * 32 + kk * 8 + d4];
            }
            __syncthreads();

#pragma unroll
            for (int d4 = 0; d4 < 8; d4++) {
                float4 qv[8];
#pragma unroll
                for (int r = 0; r < 8; r++) qv[r] = q_s4[(ty * 8 + r) * 9 + d4];
#pragma unroll
                for (int dd = 0; dd < 4; dd++) {
                    int drow = kk * 32 + d4 * 4 + dd;
                    float mv[8];
#pragma unroll
                    for (int c = 0; c < 8; c++) mv[c] = M_s[drow * 132 + c * 16 + tx];
#pragma unroll
                    for (int r = 0; r < 8; r++) {
                        float qs = f4get(qv[r], dd);
#pragma unroll
                        for (int c = 0; c < 8; c++) oacc[r][c] += qs * mv[c];
                    }
                }
            }
        }

        // Write output block
#pragma unroll
        for (int r = 0; r < 8; r++) {
            int row = qrow0 + it * 128 + ty * 8 + r;
#pragma unroll
            for (int c = 0; c < 8; c++) {
                out[row * DIM + c * 16 + tx] = oacc[r][c] * scale;
            }
        }
    }
}

// ---------------------------------------------------------------------------
extern "C" void kernel_launch(void* const* d_in, const int* in_sizes, int n_in,
                              void* d_out, int out_size)
{
    const float* x  = (const float*)d_in[0];
    const float* Wq = (const float*)d_in[1];
    const float* bq = (const float*)d_in[2];
    const float* Wk = (const float*)d_in[3];
    const float* bk = (const float*)d_in[4];
    const float* Wv = (const float*)d_in[5];
    const float* bv = (const float*)d_in[6];
    float* out = (float*)d_out;

    cudaFuncSetAttribute(qkv_proj_kernel,
                         cudaFuncAttributeMaxDynamicSharedMemorySize, P1_SMEM);
    cudaFuncSetAttribute(block_attn_kernel,
                         cudaFuncAttributeMaxDynamicSharedMemorySize, P2_SMEM);

    qkv_proj_kernel<<<dim3(NROWS / 128, 3), 256, P1_SMEM>>>(x, Wq, bq, Wk, bk, Wv, bv);
    block_attn_kernel<<<BATCH * NB, 256, P2_SMEM>>>(out);
}